// round 16
// baseline (speedup 1.0000x reference)
#include <cuda_runtime.h>
#include <math.h>
#include <stdint.h>

#define Bn   256
#define Ln   512
#define VOCAB 30000
#define EMB  100
#define HID  128
#define G4   512          // 4*HID
#define TAGS 17
#define BL   (Bn*Ln)      // 131072
#define KSMQ 14           // smem W rows per k-quarter (of 32)
#define KRGQ 18           // register W rows per k-quarter

// ---------------- scratch (device globals: allocation-free, per rules) ----------------
__device__ float g_proj[VOCAB * 1024];  // per-vocab gate preactivations, both dirs
__device__ float g_hf[BL * HID];        // forward hidden states
__device__ float g_hb[BL * HID];        // backward hidden states
__device__ float g_em[BL * TAGS];       // emissions
__device__ float g_WihT[EMB * 1024];    // W_ih transposed, dirs concatenated on cols
__device__ float g_WhhT[2 * HID * G4];  // W_hh transposed (k-major), per dir
__device__ float g_bias[1024];          // b_f ++ b_b
__device__ int   g_dummy;

// ---------------- packed f32x2 helpers ----------------
__device__ __forceinline__ uint64_t pack2(float lo, float hi) {
    uint64_t r;
    asm("mov.b64 %0, {%1, %2};" : "=l"(r) : "f"(lo), "f"(hi));
    return r;
}
__device__ __forceinline__ float2 unpack2(uint64_t v) {
    float lo, hi;
    asm("mov.b64 {%0, %1}, %2;" : "=f"(lo), "=f"(hi) : "l"(v));
    return make_float2(lo, hi);
}
__device__ __forceinline__ void ffma2(uint64_t& acc, uint64_t a, uint64_t b) {
    asm("fma.rn.f32x2 %0, %1, %2, %0;" : "+l"(acc) : "l"(a), "l"(b));
}

// ---------------- fast activations (ex2/rcp approx; ~3e-7 rel err, exact saturation) --
__device__ __forceinline__ float fsig(float x) {
    float t, r;
    asm("ex2.approx.ftz.f32 %0, %1;" : "=f"(t) : "f"(-1.4426950408889634f * x));
    asm("rcp.approx.ftz.f32 %0, %1;" : "=f"(r) : "f"(1.0f + t));
    return r;
}
__device__ __forceinline__ float ftanh(float x) {
    float t, r;
    asm("ex2.approx.ftz.f32 %0, %1;" : "=f"(t) : "f"(2.8853900817779268f * x));
    asm("rcp.approx.ftz.f32 %0, %1;" : "=f"(r) : "f"(1.0f + t));
    return 1.0f - 2.0f * r;    // (t-1)/(t+1)
}

// ---------------- filler (keeps lstm_kernel as the 4th launch for ncu capture) -------
__global__ void filler_kernel() { if (threadIdx.x == 1024) g_dummy = 1; }

// ---------------- prep: transpose weights ----------------
__global__ void prep_kernel(const float* __restrict__ Wihf, const float* __restrict__ Whhf,
                            const float* __restrict__ bf,   const float* __restrict__ Wihb,
                            const float* __restrict__ Whhb, const float* __restrict__ bb) {
    int i = blockIdx.x * blockDim.x + threadIdx.x;
    int stride = gridDim.x * blockDim.x;
    for (int idx = i; idx < EMB * 1024; idx += stride) {
        int e = idx >> 10, c = idx & 1023, d = c >> 9, j = c & 511;
        g_WihT[idx] = (d ? Wihb : Wihf)[j * EMB + e];
    }
    for (int idx = i; idx < 2 * HID * G4; idx += stride) {
        int d = idx >> 16, r = idx & 65535, k = r >> 9, j = r & 511;
        g_WhhT[idx] = (d ? Whhb : Whhf)[j * HID + k];
    }
    for (int idx = i; idx < 1024; idx += stride) {
        int d = idx >> 9, j = idx & 511;
        g_bias[idx] = (d ? bb : bf)[j];
    }
}

// ---------------- vocab projection: proj[v] = emb[v] @ W_ih^T + b (both dirs) ---------
// e processed in chunks of 4 (EMB = 100 = 25*4): per chunk 8 broadcast LDS.128 of xs
// (4x fewer xs wavefronts than scalar) + 4 LDG.128 of W. e-ascending accumulation
// order preserved exactly -> bit-identical to the previous version.
__global__ void __launch_bounds__(256) proj_kernel(const float* __restrict__ emb) {
    __shared__ float xs[64 * EMB];
    int tid = threadIdx.x;
    int rbase = blockIdx.y * 64;
    int cbase = blockIdx.x * 128;

    for (int i = tid; i < 64 * EMB; i += 256) {
        int r = i / EMB, e = i - r * EMB;
        int row = rbase + r;
        xs[i] = (row < VOCAB) ? emb[row * EMB + e] : 0.f;
    }
    __syncthreads();

    int tx = tid & 31, ty = tid >> 5;
    int c0 = cbase + tx * 4;

    uint64_t accA[8], accB[8];
    uint64_t z = pack2(0.f, 0.f);
#pragma unroll
    for (int i = 0; i < 8; i++) { accA[i] = z; accB[i] = z; }

    const float* xrow = xs + (ty * 8) * EMB;   // row stride 400B (16B aligned)
    for (int e4 = 0; e4 < EMB / 4; e4++) {
        float4 xv[8];
#pragma unroll
        for (int i = 0; i < 8; i++)
            xv[i] = *(const float4*)&xrow[i * EMB + e4 * 4];
#pragma unroll
        for (int j = 0; j < 4; j++) {
            int e = e4 * 4 + j;
            ulonglong2 w2 = *(const ulonglong2*)&g_WihT[e * 1024 + c0];
#pragma unroll
            for (int i = 0; i < 8; i++) {
                float xvf = (j == 0) ? xv[i].x : (j == 1) ? xv[i].y
                          : (j == 2) ? xv[i].z : xv[i].w;
                uint64_t xx = pack2(xvf, xvf);
                ffma2(accA[i], xx, w2.x);
                ffma2(accB[i], xx, w2.y);
            }
        }
    }

    float4 bias = *(const float4*)&g_bias[c0];
#pragma unroll
    for (int i = 0; i < 8; i++) {
        int row = rbase + ty * 8 + i;
        if (row < VOCAB) {
            float2 vA = unpack2(accA[i]);
            float2 vB = unpack2(accB[i]);
            float4 o;
            o.x = vA.x + bias.x; o.y = vA.y + bias.y;
            o.z = vB.x + bias.z; o.w = vB.y + bias.w;
            *(float4*)&g_proj[(size_t)row * 1024 + c0] = o;
        }
    }
}

// ---------------- persistent bidirectional LSTM: 512 threads, 4-way split-k ----------
extern __shared__ float lsmem[];

__global__ void __launch_bounds__(512, 1) lstm_kernel(const int* __restrict__ ids) {
    float* Wc   = lsmem;                       // 4*KSMQ*512 floats
    float* part = lsmem + 4 * KSMQ * 512;      // 4*2048 floats: [q][b][col]
    float* hbuf = part + 8192;                 // 512 floats [k][b] (16B aligned)
    int*   sids = (int*)(hbuf + 512);          // 2048 ints (pre-scaled id*1024)

    int tid   = threadIdx.x;
    int q     = tid >> 7;                      // k-quarter
    int g0    = (tid & 127) * 4;               // first of 4 gate columns
    int dir   = blockIdx.x & 1;
    int bbase = (blockIdx.x >> 1) * 4;

    const float* Wt = g_WhhT + dir * (HID * G4);

    // cooperative smem W load: Wc[(qq*KSMQ + r)][c] <- W row qq*32 + r (r < KSMQ)
    for (int i = tid; i < 4 * KSMQ * 512; i += 512) {
        int qq = i / (KSMQ * 512);
        int rem = i - qq * (KSMQ * 512);
        int r = rem >> 9, c = rem & 511;
        Wc[i] = Wt[(qq * 32 + r) * 512 + c];
    }
    hbuf[tid] = 0.f;
    for (int i = tid; i < 4 * Ln; i += 512) {
        int b = i >> 9, t = i & 511;
        sids[i] = ids[(bbase + b) * Ln + t] * 1024;   // pre-scaled row offset
    }

    // register W rows: global rows q*32 + KSMQ + j, 4 gate columns each
    float4 wreg[KRGQ];
#pragma unroll
    for (int j = 0; j < KRGQ; j++)
        wreg[j] = *(const float4*)&Wt[(q * 32 + KSMQ + j) * 512 + g0];

    float creg = 0.f;
    float* hout = dir ? g_hb : g_hf;

    const float*      wp  = Wc + q * (KSMQ * 512) + g0;
    const ulonglong2* hbp = (const ulonglong2*)hbuf;       // hbp[k] = h[k][0..3]
    int b2 = tid >> 7, k2 = tid & 127;                     // phase-2 mapping
    int dcol2 = dir * 512 + k2;                            // phase-2 proj column base
    float* pq = part + q * 2048;                           // this quarter's partials

    __syncthreads();

    for (int s = 0; s < Ln; s++) {
        int tt = dir ? (Ln - 1 - s) : s;

        // ---- issue this step's xg gather NOW; consumed in phase 2 (~3000 cyc later) --
        int rowoff = sids[b2 * 512 + tt];
        float xgi = g_proj[rowoff + dcol2];
        float xgf = g_proj[rowoff + dcol2 + 128];
        float xgg = g_proj[rowoff + dcol2 + 256];
        float xgo = g_proj[rowoff + dcol2 + 384];

        // ---- phase 1: packed partial dot products (4 cols x 2 batch-pairs) ----
        uint64_t z = pack2(0.f, 0.f);
        uint64_t a01[4], a23[4];
#pragma unroll
        for (int g = 0; g < 4; g++) { a01[g] = z; a23[g] = z; }
#pragma unroll
        for (int r = 0; r < KSMQ; r++) {
            ulonglong2 hh = hbp[q * 32 + r];        // (h0,h1)|(h2,h3), 16B broadcast
            float4 w4 = *(const float4*)(wp + r * 512);
            uint64_t w;
            w = pack2(w4.x, w4.x); ffma2(a01[0], hh.x, w); ffma2(a23[0], hh.y, w);
            w = pack2(w4.y, w4.y); ffma2(a01[1], hh.x, w); ffma2(a23[1], hh.y, w);
            w = pack2(w4.z, w4.z); ffma2(a01[2], hh.x, w); ffma2(a23[2], hh.y, w);
            w = pack2(w4.w, w4.w); ffma2(a01[3], hh.x, w); ffma2(a23[3], hh.y, w);
        }
#pragma unroll
        for (int j = 0; j < KRGQ; j++) {
            ulonglong2 hh = hbp[q * 32 + KSMQ + j];
            float4 w4 = wreg[j];
            uint64_t w;
            w = pack2(w4.x, w4.x); ffma2(a01[0], hh.x, w); ffma2(a23[0], hh.y, w);
            w = pack2(w4.y, w4.y); ffma2(a01[1], hh.x, w); ffma2(a23[1], hh.y, w);
            w = pack2(w4.z, w4.z); ffma2(a01[2], hh.x, w); ffma2(a23[2], hh.y, w);
            w = pack2(w4.w, w4.w); ffma2(a01[3], hh.x, w); ffma2(a23[3], hh.y, w);
        }
        // unpack and store per-batch float4s: part[q][b][g0..g0+3]
        float2 u01[4], u23[4];
#pragma unroll
        for (int g = 0; g < 4; g++) { u01[g] = unpack2(a01[g]); u23[g] = unpack2(a23[g]); }
        float4 pv;
        pv.x = u01[0].x; pv.y = u01[1].x; pv.z = u01[2].x; pv.w = u01[3].x;
        *(float4*)(pq + 0 * 512 + g0) = pv;
        pv.x = u01[0].y; pv.y = u01[1].y; pv.z = u01[2].y; pv.w = u01[3].y;
        *(float4*)(pq + 1 * 512 + g0) = pv;
        pv.x = u23[0].x; pv.y = u23[1].x; pv.z = u23[2].x; pv.w = u23[3].x;
        *(float4*)(pq + 2 * 512 + g0) = pv;
        pv.x = u23[0].y; pv.y = u23[1].y; pv.z = u23[2].y; pv.w = u23[3].y;
        *(float4*)(pq + 3 * 512 + g0) = pv;
        __syncthreads();

        // ---- phase 2: tree-combine 4 quarters + xg, cell update for (b2, k2) ----
        {
            const float* pb = part + b2 * 512;
            float gi = ((pb[k2]       + pb[2048 + k2])
                      + (pb[4096 + k2] + pb[6144 + k2])) + xgi;
            float gf = ((pb[128 + k2]  + pb[2048 + 128 + k2])
                      + (pb[4096 + 128 + k2] + pb[6144 + 128 + k2])) + xgf;
            float gg = ((pb[256 + k2]  + pb[2048 + 256 + k2])
                      + (pb[4096 + 256 + k2] + pb[6144 + 256 + k2])) + xgg;
            float go = ((pb[384 + k2]  + pb[2048 + 384 + k2])
                      + (pb[4096 + 384 + k2] + pb[6144 + 384 + k2])) + xgo;
            creg = fsig(gf) * creg + fsig(gi) * ftanh(gg);
            float h = fsig(go) * ftanh(creg);
            hbuf[k2 * 4 + b2] = h;
            hout[((bbase + b2) * Ln + tt) * HID + k2] = h;
        }
        __syncthreads();
    }
}

// ---------------- FC: emissions = [h_f, h_b] @ fc_W^T + fc_b ----------------
__global__ void __launch_bounds__(256) fc_kernel(const float* __restrict__ fcW,
                                                 const float* __restrict__ fcb) {
    __shared__ float wsm[TAGS * 256];
    __shared__ float fcb_s[TAGS];
    int tid = threadIdx.x;
    for (int i = tid; i < TAGS * 256; i += 256) wsm[i] = fcW[i];
    if (tid < TAGS) fcb_s[tid] = fcb[tid];
    __syncthreads();

    int lane = tid & 31, warp = tid >> 5;
    int pw = lane >> 3, sl = lane & 7;
    int pos = blockIdx.x * 32 + warp * 4 + pw;

    float4 h4[8];
    const float4* hfp = (const float4*)(g_hf + (size_t)pos * HID);
    const float4* hbp = (const float4*)(g_hb + (size_t)pos * HID);
#pragma unroll
    for (int i = 0; i < 4; i++) h4[i]     = hfp[i * 8 + sl];
#pragma unroll
    for (int i = 0; i < 4; i++) h4[4 + i] = hbp[i * 8 + sl];

    const float4* w4 = (const float4*)wsm;
    float* emrow = g_em + (size_t)pos * TAGS;
#pragma unroll
    for (int t = 0; t < TAGS; t++) {
        float s = 0.f;
#pragma unroll
        for (int i = 0; i < 8; i++) {
            float4 w = w4[t * 64 + i * 8 + sl];
            s += h4[i].x * w.x + h4[i].y * w.y + h4[i].z * w.z + h4[i].w * w.w;
        }
        s += __shfl_xor_sync(0xffffffffu, s, 1);
        s += __shfl_xor_sync(0xffffffffu, s, 2);
        s += __shfl_xor_sync(0xffffffffu, s, 4);
        if (sl == 0) emrow[t] = s + fcb_s[t];
    }
}

// ---------------- Viterbi: one warp per batch element; float32 output ----------------
__global__ void __launch_bounds__(128) viterbi_kernel(const int* __restrict__ ids,
                                                      const float* __restrict__ trans,
                                                      const float* __restrict__ start_t,
                                                      const float* __restrict__ end_t,
                                                      float* __restrict__ out) {
    __shared__ unsigned char hist[4][Ln * 20];
    int w = threadIdx.x >> 5, lane = threadIdx.x & 31;
    int b = blockIdx.x * 4 + w;
    const float NEG = -3e38f;

    float tcol[TAGS];
#pragma unroll
    for (int i = 0; i < TAGS; i++)
        tcol[i] = (lane < TAGS) ? trans[i * TAGS + lane] : 0.f;

    const float* emrow = g_em + b * Ln * TAGS;
    const int*   idrow = ids + b * Ln;

    float score = (lane < TAGS) ? start_t[lane] + emrow[lane] : NEG;

    for (int t = 1; t < Ln; t++) {
        float em = (lane < TAGS) ? emrow[t * TAGS + lane] : 0.f;
        int mask = (idrow[t] != 0);
        float best = NEG; int bi = 0;
#pragma unroll
        for (int i = 0; i < TAGS; i++) {
            float si = __shfl_sync(0xffffffffu, score, i);
            float v = si + tcol[i];
            if (v > best) { best = v; bi = i; }
        }
        int idx;
        if (mask) { if (lane < TAGS) score = best + em; idx = bi; }
        else      { idx = lane; }
        if (lane < TAGS) hist[w][t * 20 + lane] = (unsigned char)idx;
    }

    float fin = (lane < TAGS) ? score + end_t[lane] : NEG;
    int fid = lane;
#pragma unroll
    for (int off = 16; off; off >>= 1) {
        float ov = __shfl_xor_sync(0xffffffffu, fin, off);
        int   oi = __shfl_xor_sync(0xffffffffu, fid, off);
        if (ov > fin || (ov == fin && oi < fid)) { fin = ov; fid = oi; }
    }
    __syncwarp();

    if (lane == 0) {
        int tag = fid;
        float* orow = out + b * Ln;
        orow[Ln - 1] = (idrow[Ln - 1] != 0) ? (float)tag : 0.f;
        for (int t = Ln - 2; t >= 0; t--) {
            tag = hist[w][(t + 1) * 20 + tag];
            orow[t] = (idrow[t] != 0) ? (float)tag : 0.f;
        }
    }
}

// ---------------- launch ----------------
extern "C" void kernel_launch(void* const* d_in, const int* in_sizes, int n_in,
                              void* d_out, int out_size) {
    const void* p[13];
    for (int i = 0; i < 13; i++) p[i] = 0;
    int c51200 = 0, c65536 = 0, c512 = 0, c17 = 0;
    for (int i = 0; i < n_in; i++) {
        switch (in_sizes[i]) {
            case 131072:  p[0] = d_in[i]; break;
            case 3000000: p[1] = d_in[i]; break;
            case 51200:   p[(c51200++ == 0) ? 2 : 5] = d_in[i]; break;
            case 65536:   p[(c65536++ == 0) ? 3 : 6] = d_in[i]; break;
            case 512:     p[(c512++   == 0) ? 4 : 7] = d_in[i]; break;
            case 4352:    p[8]  = d_in[i]; break;
            case 289:     p[10] = d_in[i]; break;
            case 17: {
                int k = c17++;
                p[(k == 0) ? 9 : ((k == 1) ? 11 : 12)] = d_in[i];
                break;
            }
            default: break;
        }
    }
    const int*   input_ids = (const int*)  p[0];
    const float* emb       = (const float*)p[1];
    const float* Wihf      = (const float*)p[2];
    const float* Whhf      = (const float*)p[3];
    const float* bf        = (const float*)p[4];
    const float* Wihb      = (const float*)p[5];
    const float* Whhb      = (const float*)p[6];
    const float* bb        = (const float*)p[7];
    const float* fcW       = (const float*)p[8];
    const float* fcb       = (const float*)p[9];
    const float* trans     = (const float*)p[10];
    const float* startt    = (const float*)p[11];
    const float* endt      = (const float*)p[12];
    float* out = (float*)d_out;

    prep_kernel<<<64, 256>>>(Wihf, Whhf, bf, Wihb, Whhb, bb);          // launch 1
    proj_kernel<<<dim3(8, (VOCAB + 63) / 64), 256>>>(emb);             // launch 2
    filler_kernel<<<1, 32>>>();                                        // launch 3

    const int lsmem_bytes = (4 * KSMQ * 512 + 8192 + 512) * (int)sizeof(float)
                          + 4 * Ln * (int)sizeof(int);                 // 157696
    cudaFuncSetAttribute(lstm_kernel, cudaFuncAttributeMaxDynamicSharedMemorySize,
                         lsmem_bytes);
    lstm_kernel<<<128, 512, lsmem_bytes>>>(input_ids);                 // launch 4 (ncu)

    fc_kernel<<<4096, 256>>>(fcW, fcb);                                // launch 5
    viterbi_kernel<<<64, 128>>>(input_ids, trans, startt, endt, out);  // launch 6
}